// round 2
// baseline (speedup 1.0000x reference)
#include <cuda_runtime.h>
#include <cstdint>

#define NPTS  16384
#define SPTS  1024
#define KNN   32

__device__ int   g_group_idx[4*SPTS*KNN];
__device__ float g_xnorm[4*NPTS];

extern __shared__ float s_raw[];

__device__ __forceinline__ float sq3(float x, float y, float z) {
    return __fadd_rn(__fadd_rn(__fmul_rn(x, x), __fmul_rn(y, y)), __fmul_rn(z, z));
}

// ---------------------------------------------------------------- xnorm
__global__ void xnorm_kernel(const float* __restrict__ xyz) {
    int i = blockIdx.x * blockDim.x + threadIdx.x;
    if (i < 4 * NPTS)
        g_xnorm[i] = sq3(xyz[3*i], xyz[3*i+1], xyz[3*i+2]);
}

// ---------------------------------------------------------------- FPS
__global__ void __launch_bounds__(1024, 1)
fps_kernel(const float* __restrict__ xyz, float* __restrict__ out_newxyz) {
    float* sdist = s_raw;                        // NPTS
    __shared__ float s_cx, s_cy, s_cz;
    __shared__ int   s_far;
    __shared__ float swv[32];
    __shared__ int   swi[32];

    const int b = blockIdx.x, tid = threadIdx.x;
    const int lane = tid & 31, wid = tid >> 5;
    const float* xb = xyz + (size_t)b * NPTS * 3;

    float px[16], py[16], pz[16];
#pragma unroll
    for (int j = 0; j < 16; j++) {
        int p = tid + j * 1024;
        px[j] = xb[3*p]; py[j] = xb[3*p+1]; pz[j] = xb[3*p+2];
        sdist[p] = 1e10f;
    }
    if (tid == 0) { s_far = 0; s_cx = xb[0]; s_cy = xb[1]; s_cz = xb[2]; }

    for (int t = 0; t < SPTS; t++) {
        __syncthreads();
        float cx = s_cx, cy = s_cy, cz = s_cz;
        if (tid == 0) {
            out_newxyz[(b*SPTS + t)*3 + 0] = cx;
            out_newxyz[(b*SPTS + t)*3 + 1] = cy;
            out_newxyz[(b*SPTS + t)*3 + 2] = cz;
        }
        float bestd = -1.0f; int bestp = 0;
#pragma unroll
        for (int j = 0; j < 16; j++) {
            int p = tid + j * 1024;
            float d = sq3(__fadd_rn(px[j], -cx), __fadd_rn(py[j], -cy), __fadd_rn(pz[j], -cz));
            d = fminf(sdist[p], d);
            sdist[p] = d;
            if (d > bestd) { bestd = d; bestp = p; }
        }
#pragma unroll
        for (int off = 16; off; off >>= 1) {
            float od = __shfl_down_sync(~0u, bestd, off);
            int   op = __shfl_down_sync(~0u, bestp, off);
            if (od > bestd || (od == bestd && op < bestp)) { bestd = od; bestp = op; }
        }
        if (lane == 0) { swv[wid] = bestd; swi[wid] = bestp; }
        __syncthreads();
        if (wid == 0) {
            bestd = swv[lane]; bestp = swi[lane];
#pragma unroll
            for (int off = 16; off; off >>= 1) {
                float od = __shfl_down_sync(~0u, bestd, off);
                int   op = __shfl_down_sync(~0u, bestp, off);
                if (od > bestd || (od == bestd && op < bestp)) { bestd = od; bestp = op; }
            }
            if (lane == 0) {
                s_far = bestp;
                s_cx = xb[3*bestp]; s_cy = xb[3*bestp+1]; s_cz = xb[3*bestp+2];
            }
        }
    }
}

// ---------------------------------------------------------------- 32-NN
__global__ void __launch_bounds__(256, 2)
query_kernel(const float* __restrict__ xyz, const float* __restrict__ newxyz) {
    float* sd   = s_raw;            // NPTS
    float* minv = sd + NPTS;        // 256
    int*   mini = (int*)(minv + 256);

    const int cid = blockIdx.x, b = cid >> 10, tid = threadIdx.x;
    const float cx = newxyz[cid*3], cy = newxyz[cid*3+1], cz = newxyz[cid*3+2];
    const float cn = sq3(cx, cy, cz);
    const float* xb  = xyz + (size_t)b * NPTS * 3;
    const float* xnb = g_xnorm + b * NPTS;

    for (int p = tid; p < NPTS; p += 256) {
        float dot = __fadd_rn(__fadd_rn(__fmul_rn(cx, xb[3*p]), __fmul_rn(cy, xb[3*p+1])),
                              __fmul_rn(cz, xb[3*p+2]));
        sd[p] = __fadd_rn(__fadd_rn(cn, __fmul_rn(-2.0f, dot)), xnb[p]);
    }
    __syncthreads();
    {
        float bv = __int_as_float(0x7f800000); int bi = 0;
        for (int i = 0; i < 64; i++) {
            int idx = tid + (i << 8);
            float v = sd[idx];
            if (v < bv) { bv = v; bi = idx; }
        }
        minv[tid] = bv; mini[tid] = bi;
    }
    __syncthreads();
    if (tid < 32) {
        const int lane = tid;
        const float INF = __int_as_float(0x7f800000);
        int* gout = g_group_idx + (size_t)cid * KNN;
        for (int sel = 0; sel < KNN; sel++) {
            float bv = INF; int bi = 0x7fffffff;
#pragma unroll
            for (int q = 0; q < 8; q++) {
                int c = lane + (q << 5);
                float v = minv[c]; int ii = mini[c];
                if (v < bv || (v == bv && ii < bi)) { bv = v; bi = ii; }
            }
#pragma unroll
            for (int off = 16; off; off >>= 1) {
                float ov = __shfl_xor_sync(~0u, bv, off);
                int   oi = __shfl_xor_sync(~0u, bi, off);
                if (ov < bv || (ov == bv && oi < bi)) { bv = ov; bi = oi; }
            }
            if (lane == 0) { gout[sel] = bi; sd[bi] = INF; }
            __syncwarp();
            int cs = bi & 255;
            float nv = INF; int ni = 0x7fffffff;
#pragma unroll
            for (int jj = 0; jj < 2; jj++) {
                int idx = cs + ((2*lane + jj) << 8);
                float v = sd[idx];
                if (v < nv || (v == nv && idx < ni)) { nv = v; ni = idx; }
            }
#pragma unroll
            for (int off = 16; off; off >>= 1) {
                float ov = __shfl_xor_sync(~0u, nv, off);
                int   oi = __shfl_xor_sync(~0u, ni, off);
                if (ov < nv || (ov == nv && oi < ni)) { nv = ov; ni = oi; }
            }
            if (lane == 0) { minv[cs] = nv; mini[cs] = ni; }
            __syncwarp();
        }
    }
}

// ---------------------------------------------------------------- MLP
template<int CIN, int COUT, int LDX, int LDY>
__device__ __forceinline__ void layer_mm(const float* X, float* Y, const float* Wk,
                                         const float* sbias, int tid) {
    const int TPC = COUT / 4;
    const float4* W4 = (const float4*)Wk;
    const float4* b4 = (const float4*)sbias;
    for (int tile = tid; tile < 32 * TPC; tile += 256) {
        int r0 = (tile / TPC) * 2, c4 = tile % TPC;
        const float* x0 = X + r0 * LDX;
        const float* x1 = x0 + LDX;
        float4 a0 = b4[c4], a1 = a0;
#pragma unroll 4
        for (int k = 0; k < CIN; k++) {
            float4 w = W4[k * TPC + c4];
            float va = x0[k], vb = x1[k];
            a0.x = fmaf(va, w.x, a0.x); a0.y = fmaf(va, w.y, a0.y);
            a0.z = fmaf(va, w.z, a0.z); a0.w = fmaf(va, w.w, a0.w);
            a1.x = fmaf(vb, w.x, a1.x); a1.y = fmaf(vb, w.y, a1.y);
            a1.z = fmaf(vb, w.z, a1.z); a1.w = fmaf(vb, w.w, a1.w);
        }
        a0.x = fmaxf(a0.x, 0.f); a0.y = fmaxf(a0.y, 0.f); a0.z = fmaxf(a0.z, 0.f); a0.w = fmaxf(a0.w, 0.f);
        a1.x = fmaxf(a1.x, 0.f); a1.y = fmaxf(a1.y, 0.f); a1.z = fmaxf(a1.z, 0.f); a1.w = fmaxf(a1.w, 0.f);
        ((float4*)(Y + r0 * LDY))[c4] = a0;
        ((float4*)(Y + (r0 + 1) * LDY))[c4] = a1;
    }
}

template<int CIN, int COUT>
__device__ __forceinline__ void fold_bn(const float* w, const float* g, const float* b,
                                        const float* mm, const float* mv,
                                        float* Wk, float* sscale, float* sbias, int tid) {
    if (tid < COUT) {
        float s = g[tid] * rsqrtf(mv[tid] + 1e-3f);
        sscale[tid] = s;
        sbias[tid]  = b[tid] - mm[tid] * s;
    }
    __syncthreads();
    for (int i = tid; i < CIN * COUT; i += 256)
        Wk[i] = w[i] * sscale[i % COUT];
    __syncthreads();
}

__global__ void __launch_bounds__(256, 2)
mlp_kernel(const float* __restrict__ xyz, const float* __restrict__ points,
           const float* __restrict__ newxyz,
           const float* __restrict__ w0, const float* __restrict__ g0, const float* __restrict__ b0,
           const float* __restrict__ mm0, const float* __restrict__ mv0,
           const float* __restrict__ w1, const float* __restrict__ g1, const float* __restrict__ b1,
           const float* __restrict__ mm1, const float* __restrict__ mv1,
           const float* __restrict__ w2, const float* __restrict__ g2, const float* __restrict__ b2,
           const float* __restrict__ mm2, const float* __restrict__ mv2,
           float* __restrict__ out_np) {
    float* Xa = s_raw;          // 64*68
    float* Xb = Xa + 64*68;     // 64*128
    float* Wk = Xb + 64*128;    // 8192
    float* sbias  = Wk + 8192;  // 128
    float* sscale = sbias + 128;
    const int tid = threadIdx.x;

    {   // gather: 64 rows x 67 features
        int r = tid >> 2, q = tid & 3;
        int grp = blockIdx.x * 2 + (r >> 5);
        int b = grp >> 10;
        int pidx = g_group_idx[grp * KNN + (r & 31)];
        const float4* p4 = (const float4*)(points + ((size_t)b * NPTS + pidx) * 64);
        float* xr = Xa + r * 68;
#pragma unroll
        for (int m = 0; m < 4; m++) {
            float4 v = p4[q * 4 + m];
            int cc = 3 + (q * 4 + m) * 4;
            xr[cc] = v.x; xr[cc+1] = v.y; xr[cc+2] = v.z; xr[cc+3] = v.w;
        }
        if (q == 0) {
            const float* xp = xyz + ((size_t)b * NPTS + pidx) * 3;
            const float* nx = newxyz + (size_t)grp * 3;
            xr[0] = xp[0] - nx[0]; xr[1] = xp[1] - nx[1]; xr[2] = xp[2] - nx[2];
            xr[67] = 0.f;
        }
    }
    __syncthreads();
    fold_bn<67, 64>(w0, g0, b0, mm0, mv0, Wk, sscale, sbias, tid);
    layer_mm<67, 64, 68, 64>(Xa, Xb, Wk, sbias, tid);
    __syncthreads();
    fold_bn<64, 64>(w1, g1, b1, mm1, mv1, Wk, sscale, sbias, tid);
    layer_mm<64, 64, 64, 68>(Xb, Xa, Wk, sbias, tid);
    __syncthreads();
    fold_bn<64, 128>(w2, g2, b2, mm2, mv2, Wk, sscale, sbias, tid);
    layer_mm<64, 128, 68, 128>(Xa, Xb, Wk, sbias, tid);
    __syncthreads();
    {   // maxpool over K=32
        int gl = tid >> 7, c = tid & 127;
        int grp = blockIdx.x * 2 + gl;
        float m = 0.f;
#pragma unroll 8
        for (int nb = 0; nb < 32; nb++)
            m = fmaxf(m, Xb[(gl * 32 + nb) * 128 + c]);
        out_np[(size_t)grp * 128 + c] = m;
    }
}

extern "C" void kernel_launch(void* const* d_in, const int* in_sizes, int n_in,
                              void* d_out, int out_size) {
    const float* xyz    = (const float*)d_in[0];
    const float* points = (const float*)d_in[1];
    const float* w0 = (const float*)d_in[2],  *g0 = (const float*)d_in[3],
               *b0 = (const float*)d_in[4],  *mm0 = (const float*)d_in[5], *mv0 = (const float*)d_in[6];
    const float* w1 = (const float*)d_in[7],  *g1 = (const float*)d_in[8],
               *b1 = (const float*)d_in[9],  *mm1 = (const float*)d_in[10], *mv1 = (const float*)d_in[11];
    const float* w2 = (const float*)d_in[12], *g2 = (const float*)d_in[13],
               *b2 = (const float*)d_in[14], *mm2 = (const float*)d_in[15], *mv2 = (const float*)d_in[16];
    float* out = (float*)d_out;
    float* out_newxyz = out;              // [4,1024,3]
    float* out_np     = out + 4*SPTS*3;   // [4,1024,128]

    cudaFuncSetAttribute(fps_kernel,   cudaFuncAttributeMaxDynamicSharedMemorySize, NPTS*4);
    cudaFuncSetAttribute(query_kernel, cudaFuncAttributeMaxDynamicSharedMemorySize, NPTS*4 + 256*8);
    cudaFuncSetAttribute(mlp_kernel,   cudaFuncAttributeMaxDynamicSharedMemorySize, (64*68 + 64*128 + 8192 + 256)*4);

    xnorm_kernel<<<(4*NPTS + 255)/256, 256>>>(xyz);
    fps_kernel<<<4, 1024, NPTS*4>>>(xyz, out_newxyz);
    query_kernel<<<4*SPTS, 256, NPTS*4 + 256*8>>>(xyz, out_newxyz);
    mlp_kernel<<<4*SPTS/2, 256, (64*68 + 64*128 + 8192 + 256)*4>>>(
        xyz, points, out_newxyz,
        w0, g0, b0, mm0, mv0, w1, g1, b1, mm1, mv1, w2, g2, b2, mm2, mv2, out_np);
}

// round 3
// speedup vs baseline: 1.3370x; 1.3370x over previous
#include <cuda_runtime.h>
#include <cstdint>

#define NPTS  16384
#define SPTS  1024
#define KNN   32

typedef unsigned long long u64;

__device__ int   g_group_idx[4*SPTS*KNN];
__device__ float g_xnorm[4*NPTS];

extern __shared__ float s_raw[];

__device__ __forceinline__ float sq3(float x, float y, float z) {
    return __fadd_rn(__fadd_rn(__fmul_rn(x, x), __fmul_rn(y, y)), __fmul_rn(z, z));
}
__device__ __forceinline__ u64 pk(float a, float b) {
    u64 r; asm("mov.b64 %0,{%1,%2};" : "=l"(r) : "f"(a), "f"(b)); return r;
}
__device__ __forceinline__ float2 upk(u64 v) {
    float2 r; asm("mov.b64 {%0,%1},%2;" : "=f"(r.x), "=f"(r.y) : "l"(v)); return r;
}
__device__ __forceinline__ u64 add2_(u64 a, u64 b) {
    u64 r; asm("add.rn.f32x2 %0,%1,%2;" : "=l"(r) : "l"(a), "l"(b)); return r;
}
__device__ __forceinline__ u64 mul2_(u64 a, u64 b) {
    u64 r; asm("mul.rn.f32x2 %0,%1,%2;" : "=l"(r) : "l"(a), "l"(b)); return r;
}

// ---------------------------------------------------------------- xnorm
__global__ void xnorm_kernel(const float* __restrict__ xyz) {
    int i = blockIdx.x * blockDim.x + threadIdx.x;
    if (i < 4 * NPTS)
        g_xnorm[i] = sq3(xyz[3*i], xyz[3*i+1], xyz[3*i+2]);
}

// ---------------------------------------------------------------- FPS
// 512 threads, 32 pts/thread packed as 16 f32x2 pairs in registers.
// Distances (shrinking min) in smem float2; predicated write-back.
// Packed f32x2 add/mul round identically to scalar rn ops -> bit-exact.
__global__ void __launch_bounds__(512, 1)
fps_kernel(const float* __restrict__ xyz, float* __restrict__ out_newxyz) {
    float2* sd2 = (float2*)s_raw;           // 8192 float2 = 64KB
    __shared__ float s_cx, s_cy, s_cz, s_best;
    __shared__ int   s_idx;
    __shared__ float swv[16];

    const int b = blockIdx.x, tid = threadIdx.x;
    const int lane = tid & 31, wid = tid >> 5;
    const float* xb = xyz + (size_t)b * NPTS * 3;

    u64 px2[16], py2[16], pz2[16];
#pragma unroll
    for (int j = 0; j < 16; j++) {
        int p0 = j * 1024 + 2 * tid;
        px2[j] = pk(xb[3*p0],   xb[3*p0+3]);
        py2[j] = pk(xb[3*p0+1], xb[3*p0+4]);
        pz2[j] = pk(xb[3*p0+2], xb[3*p0+5]);
        sd2[j*512 + tid] = make_float2(1e10f, 1e10f);
    }
    if (tid == 0) { s_idx = 0x7fffffff; s_cx = xb[0]; s_cy = xb[1]; s_cz = xb[2]; }

    for (int t = 0; t < SPTS; t++) {
        __syncthreads();                                  // (1) centroid ready
        float cx = s_cx, cy = s_cy, cz = s_cz;
        if (tid == 0) {
            out_newxyz[(b*SPTS+t)*3+0] = cx;
            out_newxyz[(b*SPTS+t)*3+1] = cy;
            out_newxyz[(b*SPTS+t)*3+2] = cz;
        }
        u64 ncx = pk(-cx,-cx), ncy = pk(-cy,-cy), ncz = pk(-cz,-cz);
        float bestd = -1.0f;
#pragma unroll
        for (int j = 0; j < 16; j++) {
            u64 dx = add2_(px2[j], ncx);
            u64 dy = add2_(py2[j], ncy);
            u64 dz = add2_(pz2[j], ncz);
            u64 s  = add2_(add2_(mul2_(dx,dx), mul2_(dy,dy)), mul2_(dz,dz));
            float2 sf = upk(s);
            float2 od = sd2[j*512 + tid];
            float n0 = fminf(od.x, sf.x);
            float n1 = fminf(od.y, sf.y);
            if (sf.x < od.x || sf.y < od.y) sd2[j*512 + tid] = make_float2(n0, n1);
            bestd = fmaxf(bestd, fmaxf(n0, n1));
        }
        float v = bestd;
#pragma unroll
        for (int off = 16; off; off >>= 1)
            v = fmaxf(v, __shfl_xor_sync(~0u, v, off));
        if (lane == 0) swv[wid] = v;
        __syncthreads();                                  // (2)
        if (tid < 32) {
            float w = (lane < 16) ? swv[lane] : -1.0f;
#pragma unroll
            for (int off = 8; off; off >>= 1)
                w = fmaxf(w, __shfl_xor_sync(~0u, w, off));
            if (lane == 0) s_best = w;
        }
        __syncthreads();                                  // (3)
        float vstar = s_best;
        if (bestd == vstar) {                             // candidate: find first idx
            int pmin = 0x7fffffff;
#pragma unroll
            for (int j = 0; j < 16; j++) {
                float2 od = sd2[j*512 + tid];
                int p0 = j * 1024 + 2 * tid;
                if (od.y == vstar) pmin = min(pmin, p0 + 1);
                if (od.x == vstar) pmin = min(pmin, p0);
            }
            atomicMin(&s_idx, pmin);
        }
        __syncthreads();                                  // (4)
        int pw = s_idx;
        if (((pw & 1023) >> 1) == tid) {                  // owner supplies centroid from regs
            int jj = pw >> 10, ss = pw & 1;
            float vx = 0.f, vy = 0.f, vz = 0.f;
#pragma unroll
            for (int j = 0; j < 16; j++) if (j == jj) {
                float2 fx = upk(px2[j]), fy = upk(py2[j]), fz = upk(pz2[j]);
                vx = ss ? fx.y : fx.x;
                vy = ss ? fy.y : fy.x;
                vz = ss ? fz.y : fz.x;
            }
            s_cx = vx; s_cy = vy; s_cz = vz;
        }
        __syncthreads();                                  // (5)
        if (tid == 0) s_idx = 0x7fffffff;
    }
}

// ---------------------------------------------------------------- 32-NN
__global__ void __launch_bounds__(256)
query_kernel(const float* __restrict__ xyz, const float* __restrict__ newxyz) {
    float* sd   = s_raw;            // NPTS
    float* minv = sd + NPTS;        // 256
    int*   mini = (int*)(minv + 256);

    const int cid = blockIdx.x, b = cid >> 10, tid = threadIdx.x;
    const float cx = newxyz[cid*3], cy = newxyz[cid*3+1], cz = newxyz[cid*3+2];
    const float cn = sq3(cx, cy, cz);
    const float* xb  = xyz + (size_t)b * NPTS * 3;
    const float* xnb = g_xnorm + b * NPTS;

    for (int p = tid; p < NPTS; p += 256) {
        float dot = __fadd_rn(__fadd_rn(__fmul_rn(cx, xb[3*p]), __fmul_rn(cy, xb[3*p+1])),
                              __fmul_rn(cz, xb[3*p+2]));
        sd[p] = __fadd_rn(__fadd_rn(cn, __fmul_rn(-2.0f, dot)), xnb[p]);
    }
    __syncthreads();
    {
        float bv = __int_as_float(0x7f800000); int bi = 0;
        for (int i = 0; i < 64; i++) {
            int idx = tid + (i << 8);
            float v = sd[idx];
            if (v < bv) { bv = v; bi = idx; }
        }
        minv[tid] = bv; mini[tid] = bi;
    }
    __syncthreads();
    if (tid < 32) {
        const int lane = tid;
        const float INF = __int_as_float(0x7f800000);
        int* gout = g_group_idx + (size_t)cid * KNN;
        for (int sel = 0; sel < KNN; sel++) {
            float bv = INF; int bi = 0x7fffffff;
#pragma unroll
            for (int q = 0; q < 8; q++) {
                int c = lane + (q << 5);
                float v = minv[c]; int ii = mini[c];
                if (v < bv || (v == bv && ii < bi)) { bv = v; bi = ii; }
            }
#pragma unroll
            for (int off = 16; off; off >>= 1) {
                float ov = __shfl_xor_sync(~0u, bv, off);
                int   oi = __shfl_xor_sync(~0u, bi, off);
                if (ov < bv || (ov == bv && oi < bi)) { bv = ov; bi = oi; }
            }
            if (lane == 0) { gout[sel] = bi; sd[bi] = INF; }
            __syncwarp();
            int cs = bi & 255;
            float nv = INF; int ni = 0x7fffffff;
#pragma unroll
            for (int jj = 0; jj < 2; jj++) {
                int idx = cs + ((2*lane + jj) << 8);
                float v = sd[idx];
                if (v < nv || (v == nv && idx < ni)) { nv = v; ni = idx; }
            }
#pragma unroll
            for (int off = 16; off; off >>= 1) {
                float ov = __shfl_xor_sync(~0u, nv, off);
                int   oi = __shfl_xor_sync(~0u, ni, off);
                if (ov < nv || (ov == nv && oi < ni)) { nv = ov; ni = oi; }
            }
            if (lane == 0) { minv[cs] = nv; mini[cs] = ni; }
            __syncwarp();
        }
    }
}

// ---------------------------------------------------------------- MLP
#define FMA4(acc, a, w) \
    acc.x = fmaf(a, w.x, acc.x); acc.y = fmaf(a, w.y, acc.y); \
    acc.z = fmaf(a, w.z, acc.z); acc.w = fmaf(a, w.w, acc.w);

template<int CIN, int COUT, int LDX, int LDY>
__device__ __forceinline__ void layer_mm(const float* X, float* Y, const float* Wk,
                                         const float* sbias, int tid) {
    const int TPC = COUT / 4;
    const float4* W4 = (const float4*)Wk;
    const float4* b4 = (const float4*)sbias;
    for (int tile = tid; tile < 16 * TPC; tile += 256) {
        int r0 = (tile / TPC) * 4, c4 = tile % TPC;
        const float* x0 = X + r0 * LDX;
        const float* x1 = x0 + LDX;
        const float* x2 = x1 + LDX;
        const float* x3 = x2 + LDX;
        float4 acc0 = b4[c4], acc1 = acc0, acc2 = acc0, acc3 = acc0;
#pragma unroll 4
        for (int k4 = 0; k4 < CIN / 4; k4++) {
            float4 xv0 = ((const float4*)x0)[k4];
            float4 xv1 = ((const float4*)x1)[k4];
            float4 xv2 = ((const float4*)x2)[k4];
            float4 xv3 = ((const float4*)x3)[k4];
#pragma unroll
            for (int kk = 0; kk < 4; kk++) {
                float4 w = W4[(k4*4 + kk) * TPC + c4];
                float a0 = (&xv0.x)[kk], a1 = (&xv1.x)[kk];
                float a2 = (&xv2.x)[kk], a3 = (&xv3.x)[kk];
                FMA4(acc0, a0, w) FMA4(acc1, a1, w)
                FMA4(acc2, a2, w) FMA4(acc3, a3, w)
            }
        }
#pragma unroll
        for (int k = (CIN/4)*4; k < CIN; k++) {
            float4 w = W4[k * TPC + c4];
            float a0 = x0[k], a1 = x1[k], a2 = x2[k], a3 = x3[k];
            FMA4(acc0, a0, w) FMA4(acc1, a1, w)
            FMA4(acc2, a2, w) FMA4(acc3, a3, w)
        }
        acc0.x=fmaxf(acc0.x,0.f); acc0.y=fmaxf(acc0.y,0.f); acc0.z=fmaxf(acc0.z,0.f); acc0.w=fmaxf(acc0.w,0.f);
        acc1.x=fmaxf(acc1.x,0.f); acc1.y=fmaxf(acc1.y,0.f); acc1.z=fmaxf(acc1.z,0.f); acc1.w=fmaxf(acc1.w,0.f);
        acc2.x=fmaxf(acc2.x,0.f); acc2.y=fmaxf(acc2.y,0.f); acc2.z=fmaxf(acc2.z,0.f); acc2.w=fmaxf(acc2.w,0.f);
        acc3.x=fmaxf(acc3.x,0.f); acc3.y=fmaxf(acc3.y,0.f); acc3.z=fmaxf(acc3.z,0.f); acc3.w=fmaxf(acc3.w,0.f);
        ((float4*)(Y + (r0  ) * LDY))[c4] = acc0;
        ((float4*)(Y + (r0+1) * LDY))[c4] = acc1;
        ((float4*)(Y + (r0+2) * LDY))[c4] = acc2;
        ((float4*)(Y + (r0+3) * LDY))[c4] = acc3;
    }
}

template<int CIN, int COUT>
__device__ __forceinline__ void fold_bn(const float* w, const float* g, const float* b,
                                        const float* mm, const float* mv,
                                        float* Wk, float* sscale, float* sbias, int tid) {
    if (tid < COUT) {
        float s = g[tid] * rsqrtf(mv[tid] + 1e-3f);
        sscale[tid] = s;
        sbias[tid]  = b[tid] - mm[tid] * s;
    }
    __syncthreads();
    for (int i = tid; i < CIN * COUT; i += 256)
        Wk[i] = w[i] * sscale[i & (COUT - 1)];
    __syncthreads();
}

__global__ void __launch_bounds__(256, 2)
mlp_kernel(const float* __restrict__ xyz, const float* __restrict__ points,
           const float* __restrict__ newxyz,
           const float* __restrict__ w0, const float* __restrict__ g0, const float* __restrict__ b0,
           const float* __restrict__ mm0, const float* __restrict__ mv0,
           const float* __restrict__ w1, const float* __restrict__ g1, const float* __restrict__ b1,
           const float* __restrict__ mm1, const float* __restrict__ mv1,
           const float* __restrict__ w2, const float* __restrict__ g2, const float* __restrict__ b2,
           const float* __restrict__ mm2, const float* __restrict__ mv2,
           float* __restrict__ out_np) {
    float* Xa = s_raw;          // 64*68
    float* Xb = Xa + 64*68;     // 64*128
    float* Wk = Xb + 64*128;    // 8192
    float* sbias  = Wk + 8192;  // 128
    float* sscale = sbias + 128;
    const int tid = threadIdx.x;

    {   // gather: 64 rows x 67 features
        int r = tid >> 2, q = tid & 3;
        int grp = blockIdx.x * 2 + (r >> 5);
        int b = grp >> 10;
        int pidx = g_group_idx[grp * KNN + (r & 31)];
        const float4* p4 = (const float4*)(points + ((size_t)b * NPTS + pidx) * 64);
        float* xr = Xa + r * 68;
#pragma unroll
        for (int m = 0; m < 4; m++) {
            float4 v = p4[q * 4 + m];
            int cc = 3 + (q * 4 + m) * 4;
            xr[cc] = v.x; xr[cc+1] = v.y; xr[cc+2] = v.z; xr[cc+3] = v.w;
        }
        if (q == 0) {
            const float* xp = xyz + ((size_t)b * NPTS + pidx) * 3;
            const float* nx = newxyz + (size_t)grp * 3;
            xr[0] = xp[0] - nx[0]; xr[1] = xp[1] - nx[1]; xr[2] = xp[2] - nx[2];
            xr[67] = 0.f;
        }
    }
    __syncthreads();
    fold_bn<67, 64>(w0, g0, b0, mm0, mv0, Wk, sscale, sbias, tid);
    layer_mm<67, 64, 68, 64>(Xa, Xb, Wk, sbias, tid);
    __syncthreads();
    fold_bn<64, 64>(w1, g1, b1, mm1, mv1, Wk, sscale, sbias, tid);
    layer_mm<64, 64, 64, 68>(Xb, Xa, Wk, sbias, tid);
    __syncthreads();
    fold_bn<64, 128>(w2, g2, b2, mm2, mv2, Wk, sscale, sbias, tid);
    layer_mm<64, 128, 68, 128>(Xa, Xb, Wk, sbias, tid);
    __syncthreads();
    {   // maxpool over K=32
        int gl = tid >> 7, c = tid & 127;
        int grp = blockIdx.x * 2 + gl;
        float m = 0.f;
#pragma unroll 8
        for (int nb = 0; nb < 32; nb++)
            m = fmaxf(m, Xb[(gl * 32 + nb) * 128 + c]);
        out_np[(size_t)grp * 128 + c] = m;
    }
}

extern "C" void kernel_launch(void* const* d_in, const int* in_sizes, int n_in,
                              void* d_out, int out_size) {
    const float* xyz    = (const float*)d_in[0];
    const float* points = (const float*)d_in[1];
    const float* w0 = (const float*)d_in[2],  *g0 = (const float*)d_in[3],
               *b0 = (const float*)d_in[4],  *mm0 = (const float*)d_in[5], *mv0 = (const float*)d_in[6];
    const float* w1 = (const float*)d_in[7],  *g1 = (const float*)d_in[8],
               *b1 = (const float*)d_in[9],  *mm1 = (const float*)d_in[10], *mv1 = (const float*)d_in[11];
    const float* w2 = (const float*)d_in[12], *g2 = (const float*)d_in[13],
               *b2 = (const float*)d_in[14], *mm2 = (const float*)d_in[15], *mv2 = (const float*)d_in[16];
    float* out = (float*)d_out;
    float* out_newxyz = out;              // [4,1024,3]
    float* out_np     = out + 4*SPTS*3;   // [4,1024,128]

    cudaFuncSetAttribute(fps_kernel,   cudaFuncAttributeMaxDynamicSharedMemorySize, NPTS*4);
    cudaFuncSetAttribute(query_kernel, cudaFuncAttributeMaxDynamicSharedMemorySize, NPTS*4 + 256*8);
    cudaFuncSetAttribute(mlp_kernel,   cudaFuncAttributeMaxDynamicSharedMemorySize, (64*68 + 64*128 + 8192 + 256)*4);

    xnorm_kernel<<<(4*NPTS + 255)/256, 256>>>(xyz);
    fps_kernel<<<4, 512, NPTS*4>>>(xyz, out_newxyz);
    query_kernel<<<4*SPTS, 256, NPTS*4 + 256*8>>>(xyz, out_newxyz);
    mlp_kernel<<<4*SPTS/2, 256, (64*68 + 64*128 + 8192 + 256)*4>>>(
        xyz, points, out_newxyz,
        w0, g0, b0, mm0, mv0, w1, g1, b1, mm1, mv1, w2, g2, b2, mm2, mv2, out_np);
}